// round 6
// baseline (speedup 1.0000x reference)
#include <cuda_runtime.h>

#define BB 64
#define CC 512
#define TT 16
#define HWD 196
#define KK 8
#define CPB 2                 // channels per pool block
#define BCHUNK 8              // batches per chunk (51MB in + 51MB out < L2)
#define POOL_BLOCKS ((BCHUNK * CC) / CPB)   // 2048 (power of 2)

// [b][t][c] per-channel partial scores
__device__ float    g_partial[BB * TT * CC];
// [b][t] -> output slot 0..15 (0-7 = approx pos, 8-15 = 8+detail pos)
__device__ int      g_dest[BB * TT];
// per-chunk arrival counters; modulo trick => no reset needed across replays
__device__ unsigned g_ctr[BB / BCHUNK];

// ---------------------------------------------------------------------------
// Kernel 1: pool + partial-score for CPB slabs; the LAST block of the chunk
// (modulo-counter) additionally performs the per-batch reduce+select for all
// BCHUNK batches of this chunk.
// ---------------------------------------------------------------------------
__global__ __launch_bounds__(256) void k_pool(const float* __restrict__ x, int b0) {
    __shared__ float pooled[CPB * TT * 49];   // 1568
    __shared__ float sc[CPB * 49];            // 98
    __shared__ int   sm_last;

    const int bc0 = b0 * CC + blockIdx.x * CPB;
    const float* __restrict__ base = x + (size_t)bc0 * (TT * HWD);

    const int p = threadIdx.x;
    if (p < CPB * TT * 7) {                   // 224 strips
        int ch = p / 112;
        int q  = p - ch * 112;
        int t  = q / 7;
        int y  = q - t * 7;                   // pool row (input rows 2y,2y+1)
        const float4* __restrict__ src =
            (const float4*)(base + ch * (TT * HWD) + t * HWD + y * 28);
        float4 r0 = src[0], r1 = src[1], r2 = src[2], r3 = src[3];
        float4 r4 = src[4], r5 = src[5], r6 = src[6];
        float* dst = pooled + ch * (TT * 49) + t * 49 + y * 7;
        dst[0] = 0.25f * (r0.x + r0.y + r3.z + r3.w);
        dst[1] = 0.25f * (r0.z + r0.w + r4.x + r4.y);
        dst[2] = 0.25f * (r1.x + r1.y + r4.z + r4.w);
        dst[3] = 0.25f * (r1.z + r1.w + r5.x + r5.y);
        dst[4] = 0.25f * (r2.x + r2.y + r5.z + r5.w);
        dst[5] = 0.25f * (r2.z + r2.w + r6.x + r6.y);
        dst[6] = 0.25f * (r3.x + r3.y + r6.z + r6.w);
    }
    __syncthreads();

    if (threadIdx.x < CPB * 49) {
        int ch = threadIdx.x / 49, blk = threadIdx.x - ch * 49;
        const float* pc = pooled + ch * (TT * 49) + blk;
        float s = 0.f;
        #pragma unroll
        for (int t = 0; t < TT; t++) s += pc[t * 49];
        sc[threadIdx.x] = s;
    }
    __syncthreads();

    {
        const int ch = threadIdx.x >> 7;
        const int t  = (threadIdx.x >> 3) & 15;
        const int g  = threadIdx.x & 7;
        const float* pr = pooled + ch * (TT * 49) + t * 49;
        const float* sr = sc + ch * 49;
        float acc = 0.f;
        #pragma unroll
        for (int blk = g; blk < 49; blk += 8)
            acc += pr[blk] * sr[blk];
        acc += __shfl_xor_sync(0xffffffffu, acc, 4);
        acc += __shfl_xor_sync(0xffffffffu, acc, 2);
        acc += __shfl_xor_sync(0xffffffffu, acc, 1);
        if (g == 0) {
            int bc = bc0 + ch;
            int b = bc >> 9, c = bc & (CC - 1);
            g_partial[(b * TT + t) * CC + c] = acc;
        }
    }

    // ---- last-block-of-chunk does select for all BCHUNK batches ----
    __syncthreads();
    if (threadIdx.x == 0) {
        __threadfence();
        unsigned old = atomicAdd(&g_ctr[b0 / BCHUNK], 1u);
        sm_last = ((old & (POOL_BLOCKS - 1u)) == POOL_BLOCKS - 1u);
    }
    __syncthreads();
    if (!sm_last) return;
    __threadfence();

    __shared__ float v8[BCHUNK][TT];
    __shared__ int   fa8[BCHUNK][TT], fd8[BCHUNK][TT];
    const int bl = threadIdx.x >> 5;          // chunk-local batch
    const int w  = threadIdx.x & 31;
    const int t  = w >> 1;
    const int g  = w & 1;
    {
        const float* __restrict__ pp = g_partial + ((b0 + bl) * TT + t) * CC;
        float s = 0.f;
        #pragma unroll 8
        for (int j = 0; j < CC / 2; j++) s += pp[g + 2 * j];
        s += __shfl_xor_sync(0xffffffffu, s, 1);
        if (g == 0)
            v8[bl][t] = s * (1.0f / (float)(CC * TT)) + ((t & 1) == 0 ? 1.0f : 0.0f);
    }
    __syncthreads();
    if (w < TT) {
        const float mv = v8[bl][w];
        int ra = 0, rd = 0;
        #pragma unroll
        for (int j = 0; j < TT; j++) {
            float vj = v8[bl][j];
            ra += (vj > mv) || (vj == mv && j < w);
            rd += (vj < mv) || (vj == mv && j < w);
        }
        fa8[bl][w] = (ra < KK);
        fd8[bl][w] = (rd < KK);
    }
    __syncthreads();
    if (w < TT) {
        int pa = 0, pd = 0;
        for (int j = 0; j < w; j++) { pa += fa8[bl][j]; pd += fd8[bl][j]; }
        // ranks form a permutation (ra+rd==15): exactly one of fa/fd is set
        g_dest[(b0 + bl) * TT + w] = fa8[bl][w] ? pa : (KK + pd);
    }
}

// ---------------------------------------------------------------------------
// Kernel 2: per-chunk gather. Sequential READ of the chunk (expected L2 hit,
// evict-first since lines are dead after one use); permuted frame-granular
// streaming WRITE into [x_a ; x_d].
// ---------------------------------------------------------------------------
#define CHUNK4 (BCHUNK * CC * TT * (HWD / 4))   // 3,211,264 float4s

__global__ __launch_bounds__(256) void k_gather(const float* __restrict__ x,
                                                float* __restrict__ out, int b0) {
    unsigned i = blockIdx.x * 256 + threadIdx.x;
    if (i >= CHUNK4) return;
    float4 val = __ldcs(&((const float4*)x)[(size_t)b0 * (CC * TT * 49) + i]);
    unsigned hw4 = i % 49u;
    unsigned r = i / 49u;
    unsigned t = r & (TT - 1);
    unsigned c = (r >> 4) & (CC - 1);
    unsigned bl = r >> 13;
    unsigned b = b0 + bl;
    int s = __ldg(&g_dest[b * TT + t]);
    unsigned half = (unsigned)s >> 3;
    unsigned j = (unsigned)s & (KK - 1);
    unsigned o = half * (BB * CC * KK * 49u) + ((b * CC + c) * KK + j) * 49u + hw4;
    __stcs(&((float4*)out)[o], val);
}

// ---------------------------------------------------------------------------
extern "C" void kernel_launch(void* const* d_in, const int* in_sizes, int n_in,
                              void* d_out, int out_size) {
    const float* x = (const float*)d_in[0];
    float* out = (float*)d_out;

    for (int b0 = 0; b0 < BB; b0 += BCHUNK) {
        k_pool<<<POOL_BLOCKS, 256>>>(x, b0);
        k_gather<<<(CHUNK4 + 255) / 256, 256>>>(x, out, b0);
    }
}

// round 7
// speedup vs baseline: 1.3558x; 1.3558x over previous
#include <cuda_runtime.h>

#define BB 64
#define CC 512
#define TT 16
#define HWD 196
#define KK 8
#define CPB 4                               // slabs per pool unit
#define BCHUNK 8                            // batches per chunk (51MB, 2 chunks < L2)
#define NCHUNK (BB / BCHUNK)                // 8
#define POOL_UNITS ((BCHUNK * CC) / CPB)    // 1024 per chunk
#define GATH_UNITS 1024                     // (bl = u>>7, 4-channel group = u&127)
#define MAXGRID 1024

// [b][t][c] per-channel partial scores
__device__ float    g_partial[BB * TT * CC];
// per-chunk barrier counters; each launch adds exactly gridDim.x to each
// counter, so counter % gridDim.x returns to 0 after every launch (replay-safe)
__device__ unsigned g_bar[NCHUNK];

__global__ __launch_bounds__(256) void k_fused(const float* __restrict__ x,
                                               float* __restrict__ out) {
    __shared__ float pooled[CPB * TT * 49];   // 3136 floats
    __shared__ float sc[CPB * 49];            // 196
    __shared__ float v[TT];
    __shared__ int   fa[TT], fd[TT], dst_slot[TT];

    const unsigned N = gridDim.x;
    const float4* __restrict__ src4 = (const float4*)x;
    float4* __restrict__ out4 = (float4*)out;

    for (int chunk = 0; chunk < NCHUNK; chunk++) {
        const int b0 = chunk * BCHUNK;

        // ================= pool phase: chunk -> g_partial =================
        for (unsigned u = blockIdx.x; u < POOL_UNITS; u += N) {
            const int bc0 = b0 * CC + (int)u * CPB;
            const float* __restrict__ base = x + (size_t)bc0 * (TT * HWD);

            #pragma unroll
            for (int sidx = 0; sidx < 2; sidx++) {
                int s = threadIdx.x + sidx * 256;
                if (s < CPB * TT * 7) {            // 448 strips
                    int ch = s / 112;
                    int q  = s - ch * 112;
                    int t  = q / 7;
                    int y  = q - t * 7;            // pool row (input rows 2y,2y+1)
                    const float4* __restrict__ sp =
                        (const float4*)(base + (ch * TT + t) * HWD + y * 28);
                    float4 r0 = sp[0], r1 = sp[1], r2 = sp[2], r3 = sp[3];
                    float4 r4 = sp[4], r5 = sp[5], r6 = sp[6];
                    float* d = pooled + (ch * TT + t) * 49 + y * 7;
                    d[0] = 0.25f * (r0.x + r0.y + r3.z + r3.w);
                    d[1] = 0.25f * (r0.z + r0.w + r4.x + r4.y);
                    d[2] = 0.25f * (r1.x + r1.y + r4.z + r4.w);
                    d[3] = 0.25f * (r1.z + r1.w + r5.x + r5.y);
                    d[4] = 0.25f * (r2.x + r2.y + r5.z + r5.w);
                    d[5] = 0.25f * (r2.z + r2.w + r6.x + r6.y);
                    d[6] = 0.25f * (r3.x + r3.y + r6.z + r6.w);
                }
            }
            __syncthreads();

            if (threadIdx.x < CPB * 49) {          // 196 column sums
                int ch = threadIdx.x / 49, blk = threadIdx.x - ch * 49;
                const float* pc = pooled + ch * (TT * 49) + blk;
                float s = 0.f;
                #pragma unroll
                for (int t = 0; t < TT; t++) s += pc[t * 49];
                sc[threadIdx.x] = s;
            }
            __syncthreads();

            {
                const int ch = threadIdx.x >> 6;
                const int t  = (threadIdx.x >> 2) & 15;
                const int g  = threadIdx.x & 3;
                const float* pr = pooled + ch * (TT * 49) + t * 49;
                const float* sr = sc + ch * 49;
                float acc = 0.f;
                #pragma unroll
                for (int blk = g; blk < 49; blk += 4)
                    acc += pr[blk] * sr[blk];
                acc += __shfl_xor_sync(0xffffffffu, acc, 2);
                acc += __shfl_xor_sync(0xffffffffu, acc, 1);
                if (g == 0) {
                    int bc = bc0 + ch;
                    g_partial[((bc >> 9) * TT + t) * CC + (bc & (CC - 1))] = acc;
                }
            }
            __syncthreads();                       // smem reuse next unit
        }

        // ================= grid barrier (modulo counter) =================
        if (threadIdx.x == 0) {
            __threadfence();                       // publish g_partial
            atomicAdd(&g_bar[chunk], 1u);
            while ((*(volatile unsigned*)&g_bar[chunk]) % N != 0u)
                __nanosleep(128);
        }
        __syncthreads();

        // ================= gather phase: L2 re-read -> out ===============
        for (unsigned u = blockIdx.x; u < GATH_UNITS; u += N) {
            const int b  = b0 + (int)(u >> 7);
            const int c0 = (int)(u & 127) << 2;

            // scores for batch b (fixed order -> identical in all blocks)
            {
                int t = threadIdx.x >> 4, g = threadIdx.x & 15;
                const float* __restrict__ pp = g_partial + (b * TT + t) * CC;
                float s = 0.f;
                #pragma unroll
                for (int j = 0; j < CC / 16; j++) s += __ldcg(&pp[g + 16 * j]);
                s += __shfl_xor_sync(0xffffffffu, s, 8);
                s += __shfl_xor_sync(0xffffffffu, s, 4);
                s += __shfl_xor_sync(0xffffffffu, s, 2);
                s += __shfl_xor_sync(0xffffffffu, s, 1);
                if (g == 0)
                    v[t] = s * (1.0f / (float)(CC * TT)) + ((t & 1) == 0 ? 1.0f : 0.0f);
            }
            __syncthreads();
            if (threadIdx.x < TT) {                // jax top_k tie semantics
                const int i = threadIdx.x;
                const float mv = v[i];
                int ra = 0, rd = 0;
                #pragma unroll
                for (int j = 0; j < TT; j++) {
                    float vj = v[j];
                    ra += (vj > mv) || (vj == mv && j < i);
                    rd += (vj < mv) || (vj == mv && j < i);
                }
                fa[i] = (ra < KK);
                fd[i] = (rd < KK);
            }
            __syncthreads();
            if (threadIdx.x < TT) {
                const int i = threadIdx.x;
                int pa = 0, pd = 0;
                for (int j = 0; j < i; j++) { pa += fa[j]; pd += fd[j]; }
                dst_slot[i] = fa[i] ? pa : (KK + pd);   // ra+rd==15: exactly one
            }
            __syncthreads();

            // copy 4 slabs: read from L2, permuted streaming write
            for (int i = threadIdx.x; i < CPB * TT * 49; i += 256) {
                int cl = i / 784;
                int r  = i - cl * 784;
                int t  = r / 49;
                int hw4 = r - t * 49;
                float4 val = __ldcs(&src4[((size_t)(b * CC + c0 + cl) * TT + t) * 49 + hw4]);
                int s = dst_slot[t];
                unsigned half = (unsigned)s >> 3;
                unsigned j = (unsigned)s & (KK - 1);
                size_t o = (size_t)half * (BB * CC * KK * 49)
                         + ((size_t)(b * CC + c0 + cl) * KK + j) * 49 + hw4;
                __stcs(&out4[o], val);
            }
            __syncthreads();                       // v/dst_slot reuse next unit
        }
    }
}

// ---------------------------------------------------------------------------
extern "C" void kernel_launch(void* const* d_in, const int* in_sizes, int n_in,
                              void* d_out, int out_size) {
    const float* x = (const float*)d_in[0];
    float* out = (float*)d_out;

    // Host-side sizing runs at capture time only; deterministic per device.
    int dev = 0;
    cudaGetDevice(&dev);
    int nsm = 0;
    cudaDeviceGetAttribute(&nsm, cudaDevAttrMultiProcessorCount, dev);
    int bpm = 0;
    cudaOccupancyMaxActiveBlocksPerMultiprocessor(&bpm, k_fused, 256, 0);
    if (bpm < 1) bpm = 1;
    int grid = nsm * bpm;                     // guaranteed single wave
    if (grid > MAXGRID) grid = MAXGRID;

    k_fused<<<grid, 256>>>(x, out);
}

// round 8
// speedup vs baseline: 1.4919x; 1.1003x over previous
#include <cuda_runtime.h>

#define BB 64
#define CC 512
#define TT 16
#define HWD 196
#define KK 8
#define BCHUNK 8                            // batches per chunk (51MB, 2 chunks < L2)
#define NCHUNK (BB / BCHUNK)                // 8
#define CPB_P 2                             // slabs per pool unit
#define CPB_G 4                             // slabs per gather unit
#define POOL_UNITS ((BCHUNK * CC) / CPB_P)  // 2048
#define GATH_UNITS ((BCHUNK * CC) / CPB_G)  // 1024

// [b][t][c] per-channel partial scores
__device__ float    g_partial[BB * TT * CC];
// work-stealing ticket counters (monotone; modulo-decoded per launch)
__device__ unsigned g_tkp[NCHUNK];
__device__ unsigned g_tkg[NCHUNK];
// barrier counters (N adds per launch -> % N == 0 at release; replay-safe)
__device__ unsigned g_bar[NCHUNK];

__global__ __launch_bounds__(256) void k_fused(const float* __restrict__ x,
                                               float* __restrict__ out) {
    __shared__ float    pooled[CPB_P * TT * 49];   // 1568
    __shared__ float    sc[CPB_P * 49];            // 98
    __shared__ float    v[TT];
    __shared__ int      fa[TT], fd[TT], dst_slot[TT];
    __shared__ unsigned sm_u;

    const unsigned N = gridDim.x;
    const unsigned MODP = POOL_UNITS + N;
    const unsigned MODG = GATH_UNITS + N;
    const float4* __restrict__ src4 = (const float4*)x;
    float4* __restrict__ out4 = (float4*)out;

    for (int chunk = 0; chunk < NCHUNK; chunk++) {
        const int b0 = chunk * BCHUNK;

        // ============== pool phase: work-stealing over 2-slab units ==============
        for (;;) {
            if (threadIdx.x == 0)
                sm_u = atomicAdd(&g_tkp[chunk], 1u) % MODP;
            __syncthreads();
            const unsigned u = sm_u;
            if (u >= POOL_UNITS) break;

            const int bc0 = b0 * CC + (int)u * CPB_P;
            const float* __restrict__ base = x + (size_t)bc0 * (TT * HWD);

            if (threadIdx.x < CPB_P * TT * 7) {        // 224 strips
                int s  = threadIdx.x;
                int ch = s / 112;
                int q  = s - ch * 112;
                int t  = q / 7;
                int y  = q - t * 7;                    // pool row (input rows 2y,2y+1)
                const float4* __restrict__ sp =
                    (const float4*)(base + (ch * TT + t) * HWD + y * 28);
                float4 r0 = sp[0], r1 = sp[1], r2 = sp[2], r3 = sp[3];
                float4 r4 = sp[4], r5 = sp[5], r6 = sp[6];
                float* d = pooled + (ch * TT + t) * 49 + y * 7;
                d[0] = 0.25f * (r0.x + r0.y + r3.z + r3.w);
                d[1] = 0.25f * (r0.z + r0.w + r4.x + r4.y);
                d[2] = 0.25f * (r1.x + r1.y + r4.z + r4.w);
                d[3] = 0.25f * (r1.z + r1.w + r5.x + r5.y);
                d[4] = 0.25f * (r2.x + r2.y + r5.z + r5.w);
                d[5] = 0.25f * (r2.z + r2.w + r6.x + r6.y);
                d[6] = 0.25f * (r3.x + r3.y + r6.z + r6.w);
            }
            __syncthreads();

            if (threadIdx.x < CPB_P * 49) {            // 98 column sums
                int ch = threadIdx.x / 49, blk = threadIdx.x - ch * 49;
                const float* pc = pooled + ch * (TT * 49) + blk;
                float s = 0.f;
                #pragma unroll
                for (int t = 0; t < TT; t++) s += pc[t * 49];
                sc[threadIdx.x] = s;
            }
            __syncthreads();

            {
                const int ch = threadIdx.x >> 7;
                const int t  = (threadIdx.x >> 3) & 15;
                const int g  = threadIdx.x & 7;
                const float* pr = pooled + ch * (TT * 49) + t * 49;
                const float* sr = sc + ch * 49;
                float acc = 0.f;
                #pragma unroll
                for (int blk = g; blk < 49; blk += 8)
                    acc += pr[blk] * sr[blk];
                acc += __shfl_xor_sync(0xffffffffu, acc, 4);
                acc += __shfl_xor_sync(0xffffffffu, acc, 2);
                acc += __shfl_xor_sync(0xffffffffu, acc, 1);
                if (g == 0) {
                    int bc = bc0 + ch;
                    g_partial[((bc >> 9) * TT + t) * CC + (bc & (CC - 1))] = acc;
                }
            }
            __syncthreads();                           // smem/sm_u reuse
        }

        // ===================== grid barrier (modulo counter) =====================
        if (threadIdx.x == 0) {
            __threadfence();                           // publish g_partial
            atomicAdd(&g_bar[chunk], 1u);
            while ((*(volatile unsigned*)&g_bar[chunk]) % N != 0u)
                __nanosleep(64);
        }
        __syncthreads();

        // ============== gather phase: work-stealing over 4-slab units ============
        for (;;) {
            if (threadIdx.x == 0)
                sm_u = atomicAdd(&g_tkg[chunk], 1u) % MODG;
            __syncthreads();
            const unsigned u = sm_u;
            if (u >= GATH_UNITS) break;

            const int b  = b0 + (int)(u >> 7);         // 128 units per batch
            const int c0 = (int)(u & 127) << 2;        // 4 channels per unit

            // scores for batch b (fixed order -> identical in all blocks)
            {
                int t = threadIdx.x >> 4, g = threadIdx.x & 15;
                const float* __restrict__ pp = g_partial + (b * TT + t) * CC;
                float s = 0.f;
                #pragma unroll
                for (int j = 0; j < CC / 16; j++) s += __ldcg(&pp[g + 16 * j]);
                s += __shfl_xor_sync(0xffffffffu, s, 8);
                s += __shfl_xor_sync(0xffffffffu, s, 4);
                s += __shfl_xor_sync(0xffffffffu, s, 2);
                s += __shfl_xor_sync(0xffffffffu, s, 1);
                if (g == 0)
                    v[t] = s * (1.0f / (float)(CC * TT)) + ((t & 1) == 0 ? 1.0f : 0.0f);
            }
            __syncthreads();
            if (threadIdx.x < TT) {                    // jax top_k tie semantics
                const int i = threadIdx.x;
                const float mv = v[i];
                int ra = 0, rd = 0;
                #pragma unroll
                for (int j = 0; j < TT; j++) {
                    float vj = v[j];
                    ra += (vj > mv) || (vj == mv && j < i);
                    rd += (vj < mv) || (vj == mv && j < i);
                }
                fa[i] = (ra < KK);
                fd[i] = (rd < KK);
            }
            __syncthreads();
            if (threadIdx.x < TT) {
                const int i = threadIdx.x;
                int pa = 0, pd = 0;
                for (int j = 0; j < i; j++) { pa += fa[j]; pd += fd[j]; }
                dst_slot[i] = fa[i] ? pa : (KK + pd);  // ra+rd==15: exactly one
            }
            __syncthreads();

            // copy 4 slabs: read from L2 (evict-first), permuted streaming write
            for (int i = threadIdx.x; i < CPB_G * TT * 49; i += 256) {
                int cl  = i / 784;
                int r   = i - cl * 784;
                int t   = r / 49;
                int hw4 = r - t * 49;
                float4 val = __ldcs(&src4[((size_t)(b * CC + c0 + cl) * TT + t) * 49 + hw4]);
                int s = dst_slot[t];
                unsigned half = (unsigned)s >> 3;
                unsigned j = (unsigned)s & (KK - 1);
                size_t o = (size_t)half * (BB * CC * KK * 49)
                         + ((size_t)(b * CC + c0 + cl) * KK + j) * 49 + hw4;
                __stcs(&out4[o], val);
            }
            __syncthreads();                           // v/dst_slot/sm_u reuse
        }
    }
}

// ---------------------------------------------------------------------------
extern "C" void kernel_launch(void* const* d_in, const int* in_sizes, int n_in,
                              void* d_out, int out_size) {
    const float* x = (const float*)d_in[0];
    float* out = (float*)d_out;

    // Host-side sizing runs at capture time only; deterministic per device.
    int dev = 0;
    cudaGetDevice(&dev);
    int nsm = 0;
    cudaDeviceGetAttribute(&nsm, cudaDevAttrMultiProcessorCount, dev);
    int bpm = 0;
    cudaOccupancyMaxActiveBlocksPerMultiprocessor(&bpm, k_fused, 256, 0);
    if (bpm < 1) bpm = 1;
    int grid = nsm * bpm;                     // guaranteed single wave
    if (grid > 2048) grid = 2048;

    k_fused<<<grid, 256>>>(x, out);
}